// round 16
// baseline (speedup 1.0000x reference)
#include <cuda_runtime.h>
#include <cuda_bf16.h>
#include <mma.h>
#include <cstdint>

using namespace nvcuda;

// ---------------------------------------------------------------------------
// GAT (2-layer, 2-relation hetero GAT).
// Dense projections via WMMA bf16-split (HMMA path, fp32 accumulate) —
// tcgen05 is NOT available (harness PTX target sm_103 rejects it).
// Attention logits + softmax + scatter in fp32 SIMT.
//
//   NW=80000, ND=16000, H=4, F=128, fin: 256 (L0) / 128 (L1), E=200000 each.
//
// Per layer:   convA: x -> A_hi,A_lo bf16 [M,K]   (a = hi + lo)
// Per (layer, relation):
//   convB:     W [K,512] -> Bt_hi,Bt_lo bf16 [512,K] (transposed, K-major)
//   gemm_wmma: Z = A @ W  via  Ah*Bh + Ah*Bl + Al*Bh  (fp32 accum)
//   logits:    el[n,h]=x.wal[:,h], er[n,h]=x.war[:,h] (pure fp32)
//   edgeA/B/C: segment softmax + weighted scatter (head-summed)
// ---------------------------------------------------------------------------

#define NW 80000
#define ND 16000
#define HN 4
#define FF 128
#define NCOL 512   // H*F
#define MAXK 256

// -------------------------- static device scratch --------------------------
__device__ __align__(16) float         g_Z[(size_t)NW * NCOL];
__device__ __align__(16) __nv_bfloat16 g_Ahi[(size_t)NW * MAXK];
__device__ __align__(16) __nv_bfloat16 g_Alo[(size_t)NW * MAXK];
__device__ __align__(16) __nv_bfloat16 g_Bthi[NCOL * MAXK];
__device__ __align__(16) __nv_bfloat16 g_Btlo[NCOL * MAXK];
__device__ __align__(16) float         g_xw1[(size_t)NW * FF];
__device__ __align__(16) float         g_xd1[(size_t)ND * FF];
__device__ __align__(16) float         g_accW[(size_t)NW * FF];
__device__ __align__(16) float         g_accD[(size_t)ND * FF];
__device__ __align__(16) float         g_el[NW * HN];
__device__ __align__(16) float         g_er[NW * HN];
__device__ __align__(16) float         g_erd[ND * HN];
__device__ __align__(16) float         g_dummy[NW * HN];
__device__ __align__(16) unsigned      g_m[NW * HN];
__device__ __align__(16) float         g_s[NW * HN];
__device__ __align__(16) float         g_ebuf[200000 * HN];
__device__ __align__(16) float         g_wal[256 * HN];
__device__ __align__(16) float         g_war[256 * HN];

// --------------------------- generic helpers -------------------------------
__device__ __forceinline__ unsigned fflip(float f) {
    unsigned u = __float_as_uint(f);
    return (u & 0x80000000u) ? ~u : (u | 0x80000000u);
}
__device__ __forceinline__ float funflip(unsigned u) {
    u = (u & 0x80000000u) ? (u & 0x7fffffffu) : ~u;
    return __uint_as_float(u);
}

// ---------------------------- conversion kernels ---------------------------
__global__ void convA(const float* __restrict__ x, int n,
                      __nv_bfloat16* __restrict__ hi, __nv_bfloat16* __restrict__ lo) {
    int i = blockIdx.x * blockDim.x + threadIdx.x;
    if (i >= n) return;
    float a = x[i];
    __nv_bfloat16 h = __float2bfloat16(a);
    hi[i] = h;
    lo[i] = __float2bfloat16(a - __bfloat162float(h));
}

// W [K, 512] -> Bt_hi/lo [512, K] (transposed, K contiguous)
__global__ void convB(const float* __restrict__ W, int K,
                      __nv_bfloat16* __restrict__ bhi, __nv_bfloat16* __restrict__ blo) {
    int i = blockIdx.x * blockDim.x + threadIdx.x;
    if (i >= K * NCOL) return;
    int k = i >> 9;          // /512
    int n = i & (NCOL - 1);
    float a = W[i];
    __nv_bfloat16 h = __float2bfloat16(a);
    bhi[n * K + k] = h;
    blo[n * K + k] = __float2bfloat16(a - __bfloat162float(h));
}

// ------------------------------ WMMA GEMM ----------------------------------
// C[M,512] = A[M,K] @ W[K,512] with W given transposed as Bt[512,K].
// Block tile 128x128, 256 threads = 8 warps, warp tile 32x64 (2x4 of 16x16).
// BK=32, single-buffered smem, bf16-split: C += Ah*Bh + Ah*Bl + Al*Bh.
#define BK 32
#define BKP (BK + 8)   // padded row stride (bf16 elems); 80 bytes, 16B-multiple

__global__ __launch_bounds__(256, 2) void gemm_wmma(
    const __nv_bfloat16* __restrict__ Ahi, const __nv_bfloat16* __restrict__ Alo,
    const __nv_bfloat16* __restrict__ Bhi, const __nv_bfloat16* __restrict__ Blo,
    float* __restrict__ C, int M, int K) {
    __shared__ __nv_bfloat16 sAh[128][BKP];
    __shared__ __nv_bfloat16 sAl[128][BKP];
    __shared__ __nv_bfloat16 sBh[128][BKP];
    __shared__ __nv_bfloat16 sBl[128][BKP];

    int tid = threadIdx.x;
    int wid = tid >> 5;
    int wm = wid & 3;        // 4 m-groups of 32 rows
    int wn = wid >> 2;       // 2 n-groups of 64 cols
    int bm = blockIdx.y * 128;
    int bn = blockIdx.x * 128;

    wmma::fragment<wmma::accumulator, 16, 16, 16, float> acc[2][4];
#pragma unroll
    for (int i = 0; i < 2; i++)
#pragma unroll
        for (int j = 0; j < 4; j++) wmma::fill_fragment(acc[i][j], 0.0f);

    for (int k0 = 0; k0 < K; k0 += BK) {
        // load 4 tiles of [128 x 32] bf16; 512 uint4 per tile, 2 per thread
#pragma unroll
        for (int it = 0; it < 2; it++) {
            int idx = it * 256 + tid;
            int row = idx >> 2;            // 0..127
            int col = (idx & 3) * 8;       // 0,8,16,24 (bf16 elems)
            size_t ga = (size_t)(bm + row) * K + k0 + col;
            size_t gb = (size_t)(bn + row) * K + k0 + col;
            *(uint4*)&sAh[row][col] = *(const uint4*)&Ahi[ga];
            *(uint4*)&sAl[row][col] = *(const uint4*)&Alo[ga];
            *(uint4*)&sBh[row][col] = *(const uint4*)&Bhi[gb];
            *(uint4*)&sBl[row][col] = *(const uint4*)&Blo[gb];
        }
        __syncthreads();

#pragma unroll
        for (int ks = 0; ks < BK / 16; ks++) {
            wmma::fragment<wmma::matrix_a, 16, 16, 16, __nv_bfloat16, wmma::row_major> ah[2], al[2];
#pragma unroll
            for (int i = 0; i < 2; i++) {
                wmma::load_matrix_sync(ah[i], &sAh[wm * 32 + i * 16][ks * 16], BKP);
                wmma::load_matrix_sync(al[i], &sAl[wm * 32 + i * 16][ks * 16], BKP);
            }
#pragma unroll
            for (int j = 0; j < 4; j++) {
                // Bt smem holds B[n][k]; as B[k][n] it is col_major with ld = BKP
                wmma::fragment<wmma::matrix_b, 16, 16, 16, __nv_bfloat16, wmma::col_major> bh, bl;
                wmma::load_matrix_sync(bh, &sBh[wn * 64 + j * 16][ks * 16], BKP);
                wmma::load_matrix_sync(bl, &sBl[wn * 64 + j * 16][ks * 16], BKP);
#pragma unroll
                for (int i = 0; i < 2; i++) {
                    wmma::mma_sync(acc[i][j], ah[i], bh, acc[i][j]);
                    wmma::mma_sync(acc[i][j], ah[i], bl, acc[i][j]);
                    wmma::mma_sync(acc[i][j], al[i], bh, acc[i][j]);
                }
            }
        }
        __syncthreads();
    }

#pragma unroll
    for (int i = 0; i < 2; i++)
#pragma unroll
        for (int j = 0; j < 4; j++) {
            float* cp = &C[(size_t)(bm + wm * 32 + i * 16) * NCOL + bn + wn * 64 + j * 16];
            wmma::store_matrix_sync(cp, acc[i][j], NCOL, wmma::mem_row_major);
        }
}

// ------------------------------ GAT SIMT part ------------------------------
__global__ void prep_walwar(const float* __restrict__ W,
                            const float* __restrict__ al,
                            const float* __restrict__ ar,
                            int fin, float* __restrict__ wal, float* __restrict__ war) {
    int c = blockIdx.x * blockDim.x + threadIdx.x;
    if (c >= fin) return;
    const float* wrow = W + (size_t)c * NCOL;
#pragma unroll
    for (int h = 0; h < HN; h++) {
        float sl = 0.f, sr = 0.f;
        const float* wh = wrow + h * FF;
        const float* alh = al + h * FF;
        const float* arh = ar + h * FF;
        for (int f = 0; f < FF; f++) {
            float w = wh[f];
            sl += w * alh[f];
            sr += w * arh[f];
        }
        wal[c * HN + h] = sl;
        war[c * HN + h] = sr;
    }
}

__global__ void logits_kernel(const float* __restrict__ x, int fin, int n,
                              const float* __restrict__ wal, const float* __restrict__ war,
                              float* __restrict__ el, float* __restrict__ er) {
    __shared__ float swal[256 * HN];
    __shared__ float swar[256 * HN];
    for (int i = threadIdx.x; i < fin * HN; i += blockDim.x) {
        swal[i] = wal[i];
        swar[i] = war[i];
    }
    __syncthreads();

    int warp = threadIdx.x >> 5;
    int lane = threadIdx.x & 31;
    int node = blockIdx.x * (blockDim.x >> 5) + warp;
    if (node >= n) return;

    float al0 = 0, al1 = 0, al2 = 0, al3 = 0;
    float ar0 = 0, ar1 = 0, ar2 = 0, ar3 = 0;
    const float* xr = x + (size_t)node * fin;
    for (int c = lane; c < fin; c += 32) {
        float xv = xr[c];
        float4 wl = *(const float4*)&swal[c * HN];
        float4 wr = *(const float4*)&swar[c * HN];
        al0 += xv * wl.x; al1 += xv * wl.y; al2 += xv * wl.z; al3 += xv * wl.w;
        ar0 += xv * wr.x; ar1 += xv * wr.y; ar2 += xv * wr.z; ar3 += xv * wr.w;
    }
#pragma unroll
    for (int off = 16; off; off >>= 1) {
        al0 += __shfl_down_sync(0xffffffffu, al0, off);
        al1 += __shfl_down_sync(0xffffffffu, al1, off);
        al2 += __shfl_down_sync(0xffffffffu, al2, off);
        al3 += __shfl_down_sync(0xffffffffu, al3, off);
        ar0 += __shfl_down_sync(0xffffffffu, ar0, off);
        ar1 += __shfl_down_sync(0xffffffffu, ar1, off);
        ar2 += __shfl_down_sync(0xffffffffu, ar2, off);
        ar3 += __shfl_down_sync(0xffffffffu, ar3, off);
    }
    if (lane == 0) {
        el[node * HN + 0] = al0; el[node * HN + 1] = al1;
        el[node * HN + 2] = al2; el[node * HN + 3] = al3;
        er[node * HN + 0] = ar0; er[node * HN + 1] = ar1;
        er[node * HN + 2] = ar2; er[node * HN + 3] = ar3;
    }
}

__global__ void init_ms(unsigned* __restrict__ m, float* __restrict__ s, int count) {
    int i = blockIdx.x * blockDim.x + threadIdx.x;
    if (i < count) { m[i] = 0u; s[i] = 0.f; }
}

__global__ void edgeA(const float* __restrict__ el, const float* __restrict__ er,
                      const int* __restrict__ src, const int* __restrict__ dst, int E,
                      float* __restrict__ ebuf, unsigned* __restrict__ m) {
    int e = blockIdx.x * blockDim.x + threadIdx.x;
    if (e >= E) return;
    int sN = src[e], dN = dst[e];
    float4 elv = *(const float4*)&el[sN * HN];
    float4 erv = *(const float4*)&er[dN * HN];
    float v[4] = {elv.x + erv.x, elv.y + erv.y, elv.z + erv.z, elv.w + erv.w};
#pragma unroll
    for (int h = 0; h < 4; h++) {
        v[h] = v[h] > 0.f ? v[h] : 0.2f * v[h];
        atomicMax(&m[dN * HN + h], fflip(v[h]));
    }
    *(float4*)&ebuf[e * HN] = make_float4(v[0], v[1], v[2], v[3]);
}

__global__ void edgeB(float* __restrict__ ebuf, const unsigned* __restrict__ m,
                      float* __restrict__ s, const int* __restrict__ dst, int E) {
    int e = blockIdx.x * blockDim.x + threadIdx.x;
    if (e >= E) return;
    int dN = dst[e];
    float4 ev = *(float4*)&ebuf[e * HN];
    float v[4] = {ev.x, ev.y, ev.z, ev.w};
#pragma unroll
    for (int h = 0; h < 4; h++) {
        float mv = funflip(m[dN * HN + h]);
        float ex = expf(v[h] - mv);
        v[h] = ex;
        atomicAdd(&s[dN * HN + h], ex);
    }
    *(float4*)&ebuf[e * HN] = make_float4(v[0], v[1], v[2], v[3]);
}

__global__ void init_acc(float* __restrict__ acc, const float* __restrict__ b, int n) {
    int i = blockIdx.x * blockDim.x + threadIdx.x;
    if (i >= n * FF) return;
    int f = i & (FF - 1);
    acc[i] = b[f] + b[FF + f] + b[2 * FF + f] + b[3 * FF + f];
}

__global__ void edgeC(const float* __restrict__ Z, const float* __restrict__ ebuf,
                      const float* __restrict__ s,
                      const int* __restrict__ src, const int* __restrict__ dst, int E,
                      float* __restrict__ acc) {
    int warp = threadIdx.x >> 5;
    int lane = threadIdx.x & 31;
    int e = blockIdx.x * (blockDim.x >> 5) + warp;
    if (e >= E) return;
    int sN = src[e], dN = dst[e];
    float4 exv = *(const float4*)&ebuf[e * HN];
    float4 sv = *(const float4*)&s[dN * HN];
    float a0 = exv.x / sv.x, a1 = exv.y / sv.y, a2 = exv.z / sv.z, a3 = exv.w / sv.w;
    const float* z = Z + (size_t)sN * NCOL;
    float* ao = acc + (size_t)dN * FF;
#pragma unroll
    for (int j = 0; j < 4; j++) {
        int f = lane + j * 32;
        float v = z[f] * a0 + z[FF + f] * a1 + z[2 * FF + f] * a2 + z[3 * FF + f] * a3;
        atomicAdd(&ao[f], v);
    }
}

__global__ void relu_copy(const float* __restrict__ in, float* __restrict__ out, int count) {
    int i = blockIdx.x * blockDim.x + threadIdx.x;
    if (i < count) out[i] = fmaxf(in[i], 0.f);
}

// ------------------------------- host side ----------------------------------
extern "C" void kernel_launch(void* const* d_in, const int* in_sizes, int n_in,
                              void* d_out, int out_size) {
    const float* xw0 = (const float*)d_in[0];
    const float* xd0 = (const float*)d_in[1];
    const int* ww_src = (const int*)d_in[18];
    const int* ww_dst = (const int*)d_in[19];
    const int* wd_src = (const int*)d_in[20];
    const int* wd_dst = (const int*)d_in[21];
    int Eww = in_sizes[18];
    int Ewd = in_sizes[20];

    float *Z, *xw1, *xd1, *accW, *accD, *el, *er, *erd, *dummy, *s, *ebuf, *wal, *war;
    __nv_bfloat16 *Ahi, *Alo, *Bthi, *Btlo;
    unsigned* m;
    cudaGetSymbolAddress((void**)&Z, g_Z);
    cudaGetSymbolAddress((void**)&Ahi, g_Ahi);
    cudaGetSymbolAddress((void**)&Alo, g_Alo);
    cudaGetSymbolAddress((void**)&Bthi, g_Bthi);
    cudaGetSymbolAddress((void**)&Btlo, g_Btlo);
    cudaGetSymbolAddress((void**)&xw1, g_xw1);
    cudaGetSymbolAddress((void**)&xd1, g_xd1);
    cudaGetSymbolAddress((void**)&accW, g_accW);
    cudaGetSymbolAddress((void**)&accD, g_accD);
    cudaGetSymbolAddress((void**)&el, g_el);
    cudaGetSymbolAddress((void**)&er, g_er);
    cudaGetSymbolAddress((void**)&erd, g_erd);
    cudaGetSymbolAddress((void**)&dummy, g_dummy);
    cudaGetSymbolAddress((void**)&m, g_m);
    cudaGetSymbolAddress((void**)&s, g_s);
    cudaGetSymbolAddress((void**)&ebuf, g_ebuf);
    cudaGetSymbolAddress((void**)&wal, g_wal);
    cudaGetSymbolAddress((void**)&war, g_war);

    float* out_w = (float*)d_out;
    float* out_d = out_w + (size_t)NW * FF;

    dim3 gemm_grid(NCOL / 128, NW / 128);

    for (int layer = 0; layer < 2; layer++) {
        int fin = layer ? FF : 256;
        const float* in_w = layer ? xw1 : xw0;
        const float* in_d = layer ? xd1 : xd0;
        int base = 2 + layer * 8;
        const float* W_ww = (const float*)d_in[base + 0];
        const float* al_ww = (const float*)d_in[base + 1];
        const float* ar_ww = (const float*)d_in[base + 2];
        const float* b_ww = (const float*)d_in[base + 3];
        const float* W_wd = (const float*)d_in[base + 4];
        const float* al_wd = (const float*)d_in[base + 5];
        const float* ar_wd = (const float*)d_in[base + 6];
        const float* b_wd = (const float*)d_in[base + 7];

        // split-convert A once per layer (shared by both relations)
        convA<<<(NW * fin + 255) / 256, 256>>>(in_w, NW * fin, Ahi, Alo);

        // ---- relation ww (word -> word) ----
        prep_walwar<<<1, 256>>>(W_ww, al_ww, ar_ww, fin, wal, war);
        logits_kernel<<<(NW + 7) / 8, 256>>>(in_w, fin, NW, wal, war, el, er);
        init_ms<<<(NW * HN + 255) / 256, 256>>>(m, s, NW * HN);
        init_acc<<<(NW * FF + 255) / 256, 256>>>(accW, b_ww, NW);
        convB<<<(fin * NCOL + 255) / 256, 256>>>(W_ww, fin, Bthi, Btlo);
        gemm_wmma<<<gemm_grid, 256>>>(Ahi, Alo, Bthi, Btlo, Z, NW, fin);
        edgeA<<<(Eww + 255) / 256, 256>>>(el, er, ww_src, ww_dst, Eww, ebuf, m);
        edgeB<<<(Eww + 255) / 256, 256>>>(ebuf, m, s, ww_dst, Eww);
        edgeC<<<(Eww + 7) / 8, 256>>>(Z, ebuf, s, ww_src, ww_dst, Eww, accW);

        // ---- relation wd (word -> doc) ----
        prep_walwar<<<1, 256>>>(W_wd, al_wd, ar_wd, fin, wal, war);
        logits_kernel<<<(NW + 7) / 8, 256>>>(in_w, fin, NW, wal, war, el, dummy);
        logits_kernel<<<(ND + 7) / 8, 256>>>(in_d, fin, ND, wal, war, dummy, erd);
        init_ms<<<(ND * HN + 255) / 256, 256>>>(m, s, ND * HN);
        init_acc<<<(ND * FF + 255) / 256, 256>>>(accD, b_wd, ND);
        convB<<<(fin * NCOL + 255) / 256, 256>>>(W_wd, fin, Bthi, Btlo);
        gemm_wmma<<<gemm_grid, 256>>>(Ahi, Alo, Bthi, Btlo, Z, NW, fin);
        edgeA<<<(Ewd + 255) / 256, 256>>>(el, erd, wd_src, wd_dst, Ewd, ebuf, m);
        edgeB<<<(Ewd + 255) / 256, 256>>>(ebuf, m, s, wd_dst, Ewd);
        edgeC<<<(Ewd + 7) / 8, 256>>>(Z, ebuf, s, wd_src, wd_dst, Ewd, accD);

        // ---- relu / output ----
        float* ow = layer ? out_w : xw1;
        float* od = layer ? out_d : xd1;
        relu_copy<<<(NW * FF + 255) / 256, 256>>>(accW, ow, NW * FF);
        relu_copy<<<(ND * FF + 255) / 256, 256>>>(accD, od, ND * FF);
    }
}